// round 12
// baseline (speedup 1.0000x reference)
#include <cuda_runtime.h>
#include <cuda_fp16.h>
#include <cstdint>

#define BB 512
#define TT 256
#define CC 128
#define HH 128
#define BTH (BB * TT * HH)   // 16,777,216

// q fp16 scratch (cross-warp layout exchange; L2-hot)
__device__ __half g_qh[(size_t)BTH];  // q * QSCALE, [b][t][h]

__device__ __forceinline__ uint32_t h2bits(float a, float b) {
    __half2 h = __floats2half2_rn(a, b);
    return *(uint32_t*)&h;
}
__device__ __forceinline__ uint32_t smem_u32(const void* p) {
    uint32_t a;
    asm("{ .reg .u64 t; cvta.to.shared.u64 t, %1; cvt.u32.u64 %0, t; }" : "=r"(a) : "l"(p));
    return a;
}

// m16n8k16 fp16 MMA, fp32 accumulate in place
__device__ __forceinline__ void mma_f16(float acc[4], const uint32_t a[4],
                                        uint32_t b0, uint32_t b1) {
    asm volatile(
        "mma.sync.aligned.m16n8k16.row.col.f32.f16.f16.f32 "
        "{%0,%1,%2,%3}, {%4,%5,%6,%7}, {%8,%9}, {%0,%1,%2,%3};"
        : "+f"(acc[0]), "+f"(acc[1]), "+f"(acc[2]), "+f"(acc[3])
        : "r"(a[0]), "r"(a[1]), "r"(a[2]), "r"(a[3]), "r"(b0), "r"(b1));
}

// ldmatrix x4: four 8x8 b16 tiles, one shared-pipe op
__device__ __forceinline__ void ldsm_x4(uint32_t r[4], uint32_t addr) {
    asm volatile("ldmatrix.sync.aligned.m8n8.x4.shared.b16 {%0,%1,%2,%3}, [%4];"
                 : "=r"(r[0]), "=r"(r[1]), "=r"(r[2]), "=r"(r[3]) : "r"(addr));
}

// scale * log2(e): softmax computed base-2; folded into q at projection time
#define QSCALE (0.08838834764831845f * 1.4426950408889634f)

#define THREADS 512
#define LWB 136
#define LVT 264
#define XBUF_OFF 0
#define WBUF_OFF (128 * LWB)
#define KSM_OFF  (WBUF_OFF + 128 * LWB)
#define VT_OFF   (KSM_OFF + 256 * LWB)
#define FUSED_SMEM ((VT_OFF + 128 * LVT) * 2)
#define NEG_BIG (-1.0e30f)

// ---- prefetch helpers: gmem -> regs (fp16-packed), regs -> smem ----
// W: per-thread 8 chunks of 4 consecutive K-rows at one n. (transposed store)
__device__ __forceinline__ void ldg_w(const float* __restrict__ W, uint2 r[8], int tid) {
#pragma unroll
    for (int j = 0; j < 8; j++) {
        int i  = tid + j * THREADS;    // 0..4095
        int n  = i & 127;
        int kq = i >> 7;               // 0..31
        float w0 = W[(kq * 4 + 0) * HH + n];
        float w1 = W[(kq * 4 + 1) * HH + n];
        float w2 = W[(kq * 4 + 2) * HH + n];
        float w3 = W[(kq * 4 + 3) * HH + n];
        r[j] = make_uint2(h2bits(w0, w1), h2bits(w2, w3));
    }
}
__device__ __forceinline__ void sts_w(const uint2 r[8], __half* __restrict__ ws, int tid) {
#pragma unroll
    for (int j = 0; j < 8; j++) {
        int i  = tid + j * THREADS;
        int n  = i & 127;
        int kq = i >> 7;
        *(uint2*)&ws[n * LWB + kq * 4] = r[j];
    }
}
// x: per-thread 8 float4 chunks (row-major)
__device__ __forceinline__ void ldg_x(const float* __restrict__ xsrc, uint2 r[8], int tid) {
    const float4* xg = (const float4*)xsrc;
#pragma unroll
    for (int j = 0; j < 8; j++) {
        float4 v = xg[tid + j * THREADS];
        r[j] = make_uint2(h2bits(v.x, v.y), h2bits(v.z, v.w));
    }
}
__device__ __forceinline__ void sts_x(const uint2 r[8], __half* __restrict__ xs, int tid) {
#pragma unroll
    for (int j = 0; j < 8; j++) {
        int i4  = tid + j * THREADS;
        int row = i4 >> 5;
        int c4  = (i4 & 31) * 4;
        *(uint2*)&xs[row * LWB + c4] = r[j];
    }
}

__global__ void __launch_bounds__(THREADS, 1)
fused_head(const float* __restrict__ x,
           const float* __restrict__ Wk,
           const float* __restrict__ Wq,
           const float* __restrict__ Wv,
           float* __restrict__ outg,
           float* __restrict__ kout,
           float* __restrict__ vout)
{
    extern __shared__ __half smh[];
    __half* xbuf = smh + XBUF_OFF;    // [128][136]
    __half* Wbuf = smh + WBUF_OFF;    // [128][136]
    __half* ksm  = smh + KSM_OFF;     // [256][136]
    __half* vtsm = smh + VT_OFF;      // [128][264]
    __half* qsm  = smh + XBUF_OFF;    // overlay after proj: [256][136]

    const int tid  = threadIdx.x;
    const int b    = blockIdx.x;
    const int w    = tid >> 5;        // 0..15
    const int lane = tid & 31;
    const int g    = lane >> 2;
    const int c    = lane & 3;
    const int mbase = (w >> 1) * 16;
    const int nbase = (w & 1) * 64;
    const int rb   = w * 16;

    const int arow = (lane & 7) + ((lane >> 3) & 1) * 8;
    const int acol = (lane >> 4) * 8;
    const int brow = (lane & 7) + (lane >> 4) * 8;
    const int bcol = ((lane >> 3) & 1) * 8;

    const uint32_t xs_a = smem_u32(xbuf);
    const uint32_t wb_a = smem_u32(Wbuf);
    const uint32_t ks_a = smem_u32(ksm);
    const uint32_t vt_a = smem_u32(vtsm);

    // =======================================================================
    // Phase P: projection with register prefetch of x/W
    // =======================================================================
    const uint32_t xa_base  = xs_a + (uint32_t)((mbase + arow) * LWB + acol) * 2u;
    const uint32_t wbB_base = wb_a + (uint32_t)((nbase + brow) * LWB + bcol) * 2u;
    const float* Wseq[3] = {Wk, Wq, Wv};

    uint2 xreg[8], wreg[8];
    ldg_x(x + (size_t)b * TT * CC, xreg, tid);
    ldg_w(Wk, wreg, tid);

#pragma unroll 1
    for (int half = 0; half < 2; half++) {
        __syncthreads();               // prior readers of xbuf/Wbuf done
        sts_x(xreg, xbuf, tid);
        if (half == 0) ldg_x(x + ((size_t)b * TT + 128) * CC, xreg, tid);

#pragma unroll 1
        for (int ph = 0; ph < 3; ph++) {
            if (ph > 0) __syncthreads();   // prev phase Wbuf readers done
            sts_w(wreg, Wbuf, tid);
            // prefetch next W (sequence: Wq, Wv, [Wk for half1], Wq, Wv)
            if (ph < 2)                  ldg_w(Wseq[ph + 1], wreg, tid);
            else if (half == 0)          ldg_w(Wk, wreg, tid);
            __syncthreads();

            float acc[8][4];
#pragma unroll
            for (int nt = 0; nt < 8; nt++)
#pragma unroll
                for (int e = 0; e < 4; e++) acc[nt][e] = 0.0f;

#pragma unroll
            for (int kk = 0; kk < 8; kk++) {
                uint32_t a0[4];
                ldsm_x4(a0, xa_base + (uint32_t)kk * 32u);
#pragma unroll
                for (int ntp = 0; ntp < 4; ntp++) {
                    uint32_t b4[4];
                    ldsm_x4(b4, wbB_base + (uint32_t)(ntp * 16 * LWB) * 2u + (uint32_t)kk * 32u);
                    mma_f16(acc[2 * ntp],     a0, b4[0], b4[1]);
                    mma_f16(acc[2 * ntp + 1], a0, b4[2], b4[3]);
                }
            }

            // epilogue (warp rows: mbase+g, +8)
#pragma unroll
            for (int nt = 0; nt < 8; nt++) {
                int rloc = mbase + g;
                int t    = half * 128 + rloc;
                int grow = b * TT + t;
                int col  = nbase + nt * 8 + 2 * c;
                const float* v4 = acc[nt];
                if (ph == 0) {          // k
                    *(float2*)(kout + (size_t)grow * HH + col)       = make_float2(v4[0], v4[1]);
                    *(float2*)(kout + (size_t)(grow + 8) * HH + col) = make_float2(v4[2], v4[3]);
                    *(uint32_t*)&ksm[t * LWB + col]       = h2bits(v4[0], v4[1]);
                    *(uint32_t*)&ksm[(t + 8) * LWB + col] = h2bits(v4[2], v4[3]);
                } else if (ph == 1) {   // q (pre-scaled)
                    *(uint32_t*)&g_qh[(size_t)grow * HH + col]       = h2bits(v4[0] * QSCALE, v4[1] * QSCALE);
                    *(uint32_t*)&g_qh[(size_t)(grow + 8) * HH + col] = h2bits(v4[2] * QSCALE, v4[3] * QSCALE);
                } else {                // v
                    *(float2*)(vout + (size_t)grow * HH + col)       = make_float2(v4[0], v4[1]);
                    *(float2*)(vout + (size_t)(grow + 8) * HH + col) = make_float2(v4[2], v4[3]);
                    vtsm[(col    ) * LVT + t]     = __float2half_rn(v4[0]);
                    vtsm[(col + 1) * LVT + t]     = __float2half_rn(v4[1]);
                    vtsm[(col    ) * LVT + t + 8] = __float2half_rn(v4[2]);
                    vtsm[(col + 1) * LVT + t + 8] = __float2half_rn(v4[3]);
                }
            }
        }
    }
    __syncthreads();

    // ---- copy this batch's q into qsm overlay ([256][136]) ----
    {
        const __half* qg = g_qh + (size_t)b * TT * HH;
#pragma unroll
        for (int j = 0; j < 8; j++) {
            int i4  = tid + j * THREADS;
            int row = i4 >> 4;
            int c8  = (i4 & 15) * 8;
            *(uint4*)&qsm[row * LWB + c8] = *(const uint4*)&qg[(size_t)row * HH + c8];
        }
    }
    __syncthreads();

    // =======================================================================
    // Phase A: causal flash attention; warp w: rows rb..rb+15
    //   full tiles kt=0..w/4-1 (no masking), then diagonal tile (partial).
    // =======================================================================
    const uint32_t qa_base  = smem_u32(qsm) + (uint32_t)((rb + arow) * LWB + acol) * 2u;
    const uint32_t ksB_base = ks_a + (uint32_t)(brow * LWB + bcol) * 2u;
    const uint32_t vtB_base = vt_a + (uint32_t)(brow * LVT + bcol) * 2u;

    float m0 = NEG_BIG, m1 = NEG_BIG, l0 = 0.0f, l1 = 0.0f;
    float o[16][4];
#pragma unroll
    for (int nt = 0; nt < 16; nt++)
#pragma unroll
        for (int e = 0; e < 4; e++) o[nt][e] = 0.0f;

    const int row0 = rb + g;
    const int row1 = row0 + 8;
    const int full = w >> 2;     // number of fully-unmasked key tiles
    const int dm   = w & 3;      // diagonal sub-position (0..3)

    float s[8][4];

    // --- softmax + PV for one key tile; S already masked in s[] ---
    auto softmax_update = [&](void) {
        float mx0 = NEG_BIG, mx1 = NEG_BIG;
#pragma unroll
        for (int nt = 0; nt < 8; nt++) {
            mx0 = fmaxf(mx0, fmaxf(s[nt][0], s[nt][1]));
            mx1 = fmaxf(mx1, fmaxf(s[nt][2], s[nt][3]));
        }
#pragma unroll
        for (int off = 1; off < 4; off <<= 1) {
            mx0 = fmaxf(mx0, __shfl_xor_sync(0xffffffffu, mx0, off));
            mx1 = fmaxf(mx1, __shfl_xor_sync(0xffffffffu, mx1, off));
        }
        float mn0 = fmaxf(m0, mx0);
        float mn1 = fmaxf(m1, mx1);
        float al0 = exp2f(m0 - mn0);
        float al1 = exp2f(m1 - mn1);
        float ps0 = 0.0f, ps1 = 0.0f;
#pragma unroll
        for (int nt = 0; nt < 8; nt++) {
            s[nt][0] = exp2f(s[nt][0] - mn0);
            s[nt][1] = exp2f(s[nt][1] - mn0);
            s[nt][2] = exp2f(s[nt][2] - mn1);
            s[nt][3] = exp2f(s[nt][3] - mn1);
            ps0 += s[nt][0] + s[nt][1];
            ps1 += s[nt][2] + s[nt][3];
        }
#pragma unroll
        for (int off = 1; off < 4; off <<= 1) {
            ps0 += __shfl_xor_sync(0xffffffffu, ps0, off);
            ps1 += __shfl_xor_sync(0xffffffffu, ps1, off);
        }
        l0 = l0 * al0 + ps0;
        l1 = l1 * al1 + ps1;
        m0 = mn0;
        m1 = mn1;
#pragma unroll
        for (int nt = 0; nt < 16; nt++) {
            o[nt][0] *= al0;
            o[nt][1] *= al0;
            o[nt][2] *= al1;
            o[nt][3] *= al1;
        }
    };

    // ---- full (unmasked) key tiles ----
#pragma unroll 1
    for (int kt = 0; kt < full; kt++) {
#pragma unroll
        for (int nt = 0; nt < 8; nt++)
#pragma unroll
            for (int e = 0; e < 4; e++) s[nt][e] = 0.0f;

        const uint32_t kbase = ksB_base + (uint32_t)(kt * 64 * LWB) * 2u;
#pragma unroll
        for (int kk = 0; kk < 8; kk++) {
            uint32_t aq[4];
            ldsm_x4(aq, qa_base + (uint32_t)kk * 32u);
#pragma unroll
            for (int ntp = 0; ntp < 4; ntp++) {
                uint32_t b4[4];
                ldsm_x4(b4, kbase + (uint32_t)(ntp * 16 * LWB) * 2u + (uint32_t)kk * 32u);
                mma_f16(s[2 * ntp],     aq, b4[0], b4[1]);
                mma_f16(s[2 * ntp + 1], aq, b4[2], b4[3]);
            }
        }

        softmax_update();

        const uint32_t vbase = vtB_base + (uint32_t)(kt * 64) * 2u;
#pragma unroll
        for (int kk = 0; kk < 4; kk++) {
            uint32_t pa[4];
            pa[0] = h2bits(s[2 * kk][0],     s[2 * kk][1]);
            pa[1] = h2bits(s[2 * kk][2],     s[2 * kk][3]);
            pa[2] = h2bits(s[2 * kk + 1][0], s[2 * kk + 1][1]);
            pa[3] = h2bits(s[2 * kk + 1][2], s[2 * kk + 1][3]);
#pragma unroll
            for (int ntp = 0; ntp < 8; ntp++) {
                uint32_t b4[4];
                ldsm_x4(b4, vbase + (uint32_t)(ntp * 16 * LVT) * 2u + (uint32_t)kk * 32u);
                mma_f16(o[2 * ntp],     pa, b4[0], b4[1]);
                mma_f16(o[2 * ntp + 1], pa, b4[2], b4[3]);
            }
        }
    }

    // ---- diagonal tile (kt = full): only ntp/kk <= dm carry signal ----
    {
#pragma unroll
        for (int nt = 0; nt < 8; nt++)
#pragma unroll
            for (int e = 0; e < 4; e++) s[nt][e] = 0.0f;

        const uint32_t kbase = ksB_base + (uint32_t)(full * 64 * LWB) * 2u;
#pragma unroll
        for (int kk = 0; kk < 8; kk++) {
            uint32_t aq[4];
            ldsm_x4(aq, qa_base + (uint32_t)kk * 32u);
#pragma unroll 4
            for (int ntp = 0; ntp <= dm; ntp++) {
                uint32_t b4[4];
                ldsm_x4(b4, kbase + (uint32_t)(ntp * 16 * LWB) * 2u + (uint32_t)kk * 32u);
                mma_f16(s[2 * ntp],     aq, b4[0], b4[1]);
                mma_f16(s[2 * ntp + 1], aq, b4[2], b4[3]);
            }
        }

        // mask (diagonal only)
#pragma unroll
        for (int nt = 0; nt < 8; nt++) {
            int k0 = full * 64 + nt * 8 + 2 * c;
            s[nt][0] = (nt <= 2 * dm + 1 && k0     <= row0) ? s[nt][0] : NEG_BIG;
            s[nt][1] = (nt <= 2 * dm + 1 && k0 + 1 <= row0) ? s[nt][1] : NEG_BIG;
            s[nt][2] = (nt <= 2 * dm + 1 && k0     <= row1) ? s[nt][2] : NEG_BIG;
            s[nt][3] = (nt <= 2 * dm + 1 && k0 + 1 <= row1) ? s[nt][3] : NEG_BIG;
        }

        softmax_update();

        const uint32_t vbase = vtB_base + (uint32_t)(full * 64) * 2u;
#pragma unroll 4
        for (int kk = 0; kk <= dm; kk++) {
            uint32_t pa[4];
            pa[0] = h2bits(s[2 * kk][0],     s[2 * kk][1]);
            pa[1] = h2bits(s[2 * kk][2],     s[2 * kk][3]);
            pa[2] = h2bits(s[2 * kk + 1][0], s[2 * kk + 1][1]);
            pa[3] = h2bits(s[2 * kk + 1][2], s[2 * kk + 1][3]);
#pragma unroll
            for (int ntp = 0; ntp < 8; ntp++) {
                uint32_t b4[4];
                ldsm_x4(b4, vbase + (uint32_t)(ntp * 16 * LVT) * 2u + (uint32_t)kk * 32u);
                mma_f16(o[2 * ntp],     pa, b4[0], b4[1]);
                mma_f16(o[2 * ntp + 1], pa, b4[2], b4[3]);
            }
        }
    }

    // ---- normalize + write ----
    float inv0 = 1.0f / l0;
    float inv1 = 1.0f / l1;
    float* orow0 = outg + ((size_t)b * TT + rb + g) * HH;
    float* orow1 = orow0 + 8 * HH;
#pragma unroll
    for (int nt = 0; nt < 16; nt++) {
        int col = nt * 8 + 2 * c;
        *(float2*)(orow0 + col) = make_float2(o[nt][0] * inv0, o[nt][1] * inv0);
        *(float2*)(orow1 + col) = make_float2(o[nt][2] * inv1, o[nt][3] * inv1);
    }
}

// ===========================================================================
extern "C" void kernel_launch(void* const* d_in, const int* in_sizes, int n_in,
                              void* d_out, int out_size)
{
    const float* x  = (const float*)d_in[0];
    const float* Wk = (const float*)d_in[1];
    const float* Wq = (const float*)d_in[2];
    const float* Wv = (const float*)d_in[3];

    float* out  = (float*)d_out;
    float* kout = out + (size_t)BTH;
    float* vout = out + 2 * (size_t)BTH;

    cudaFuncSetAttribute(fused_head, cudaFuncAttributeMaxDynamicSharedMemorySize, FUSED_SMEM);
    fused_head<<<BB, THREADS, FUSED_SMEM>>>(x, Wk, Wq, Wv, out, kout, vout);
}